// round 12
// baseline (speedup 1.0000x reference)
#include <cuda_runtime.h>
#include <cstdint>

#define RES 256
#define N_TOTAL (8 * 65536)

__device__ __forceinline__ uint64_t evict_last_policy() {
    uint64_t pol;
    asm("createpolicy.fractional.L2::evict_last.b64 %0, 1.0;" : "=l"(pol));
    return pol;
}

__device__ __forceinline__ float4 ldg_keep4(const float* p, uint64_t pol) {
    float4 v;
    asm volatile("ld.global.nc.L2::cache_hint.v4.f32 {%0,%1,%2,%3}, [%4], %5;"
                 : "=f"(v.x), "=f"(v.y), "=f"(v.z), "=f"(v.w)
                 : "l"(p), "l"(pol));
    return v;
}

__device__ __forceinline__ float ldg_keep(const float* p, uint64_t pol) {
    float v;
    asm volatile("ld.global.nc.L2::cache_hint.f32 %0, [%1], %2;"
                 : "=f"(v) : "l"(p), "l"(pol));
    return v;
}

__device__ __forceinline__ float sel4(float4 v, int o) {
    float r = (o == 1) ? v.y : v.x;
    r = (o == 2) ? v.z : r;
    r = (o == 3) ? v.w : r;
    return r;
}

__global__ __launch_bounds__(256) void volume_sample_kernel(
    const float* __restrict__ x,
    const float* __restrict__ vol,
    float* __restrict__ out)
{
    int i = blockIdx.x * blockDim.x + threadIdx.x;
    if (i >= N_TOTAL) return;

    uint64_t pol = evict_last_policy();

    // coords: plain __ldg -> stay L2-resident across graph replays
    // (R4 used __ldcs/evict-first, forcing a DRAM refetch burst at each replay head)
    float gx = __ldg(x + 3 * i + 0);
    float gy = __ldg(x + 3 * i + 1);
    float gz = __ldg(x + 3 * i + 2);

    // EXTENT=0.5 fold: ix = 256*gx + 127.5
    float ix = fmaf(gx, 256.0f, 127.5f);
    float iy = fmaf(gy, 256.0f, 127.5f);
    float iz = fmaf(gz, 256.0f, 127.5f);

    float fx0 = floorf(ix), fy0 = floorf(iy), fz0 = floorf(iz);
    float tx = ix - fx0, ty = iy - fy0, tz = iz - fz0;

    int x0 = (int)fx0, y0 = (int)fy0, z0 = (int)fz0;
    int x1 = x0 + 1,   y1 = y0 + 1,   z1 = z0 + 1;

    // ---- address math first, loads issued as early as possible ----
    int cx0 = min(max(x0, 0), RES - 1);
    int cx1 = min(max(x1, 0), RES - 1);
    int cy0 = min(max(y0, 0), RES - 1);
    int cy1 = min(max(y1, 0), RES - 1);
    int cz0 = min(max(z0, 0), RES - 1);
    int cz1 = min(max(z1, 0), RES - 1);

    int pz0 = cz0 << 16;
    int pz1 = cz1 << 16;
    int r00 = pz0 + (cy0 << 8);   // (z0, y0)
    int r01 = pz0 + (cy1 << 8);   // (z0, y1)
    int r10 = pz1 + (cy0 << 8);   // (z1, y0)
    int r11 = pz1 + (cy1 << 8);   // (z1, y1)

    int base = cx0 & ~3;          // 16B-aligned; base+3 <= 255 always
    int ao = cx0 - base;          // 0..3
    int d1 = cx1 - base;          // 0..4
    int bo = min(d1, 3);
    bool need_extra = (d1 == 4);  // ~25% of lanes

    // 4 vector gathers in flight before any mask ALU
    float4 q00 = ldg_keep4(vol + r00 + base, pol);
    float4 q01 = ldg_keep4(vol + r01 + base, pol);
    float4 q10 = ldg_keep4(vol + r10 + base, pol);
    float4 q11 = ldg_keep4(vol + r11 + base, pol);

    float e00 = 0.f, e01 = 0.f, e10 = 0.f, e11 = 0.f;
    if (need_extra) {
        e00 = ldg_keep(vol + r00 + cx1, pol);
        e01 = ldg_keep(vol + r01 + cx1, pol);
        e10 = ldg_keep(vol + r10 + cx1, pol);
        e11 = ldg_keep(vol + r11 + cx1, pol);
    }

    // ---- masks computed while loads are outstanding ----
    bool vx0 = (x0 >= 0) & (x0 < RES);
    bool vx1 = (x1 >= 0) & (x1 < RES);
    bool vy0 = (y0 >= 0) & (y0 < RES);
    bool vy1 = (y1 >= 0) & (y1 < RES);
    bool vz0 = (z0 >= 0) & (z0 < RES);
    bool vz1 = (z1 >= 0) & (z1 < RES);

    float a00 = sel4(q00, ao), a01 = sel4(q01, ao);
    float a10 = sel4(q10, ao), a11 = sel4(q11, ao);
    float b00 = need_extra ? e00 : sel4(q00, bo);
    float b01 = need_extra ? e01 : sel4(q01, bo);
    float b10 = need_extra ? e10 : sel4(q10, bo);
    float b11 = need_extra ? e11 : sel4(q11, bo);

    a00 = (vz0 & vy0 & vx0) ? a00 : 0.0f;
    b00 = (vz0 & vy0 & vx1) ? b00 : 0.0f;
    a01 = (vz0 & vy1 & vx0) ? a01 : 0.0f;
    b01 = (vz0 & vy1 & vx1) ? b01 : 0.0f;
    a10 = (vz1 & vy0 & vx0) ? a10 : 0.0f;
    b10 = (vz1 & vy0 & vx1) ? b10 : 0.0f;
    a11 = (vz1 & vy1 & vx0) ? a11 : 0.0f;
    b11 = (vz1 & vy1 & vx1) ? b11 : 0.0f;

    float c00 = fmaf(tx, b00 - a00, a00);
    float c01 = fmaf(tx, b01 - a01, a01);
    float c10 = fmaf(tx, b10 - a10, a10);
    float c11 = fmaf(tx, b11 - a11, a11);

    float c0 = fmaf(ty, c01 - c00, c00);
    float c1 = fmaf(ty, c11 - c10, c10);
    float c  = fmaf(tz, c1 - c0, c0);

    float r = 100.0f * c;
    asm volatile("st.global.cs.f32 [%0], %1;" :: "l"(out + i), "f"(r) : "memory");
}

extern "C" void kernel_launch(void* const* d_in, const int* in_sizes, int n_in,
                              void* d_out, int out_size)
{
    const float* x   = (const float*)d_in[0];  // [8, 65536, 3] f32
    const float* vol = (const float*)d_in[1];  // [256,256,256] f32
    float* out = (float*)d_out;                // [8, 65536] f32

    int threads = 256;
    int blocks  = (N_TOTAL + threads - 1) / threads;   // 2048
    volume_sample_kernel<<<blocks, threads>>>(x, vol, out);
}

// round 13
// speedup vs baseline: 1.3953x; 1.3953x over previous
#include <cuda_runtime.h>
#include <cstdint>

#define RES 256
#define N_TOTAL (8 * 65536)

__device__ __forceinline__ uint64_t evict_last_policy() {
    uint64_t pol;
    asm("createpolicy.fractional.L2::evict_last.b64 %0, 1.0;" : "=l"(pol));
    return pol;
}

__device__ __forceinline__ float4 ldg_keep4(const float* p, uint64_t pol) {
    float4 v;
    asm volatile("ld.global.nc.L2::cache_hint.v4.f32 {%0,%1,%2,%3}, [%4], %5;"
                 : "=f"(v.x), "=f"(v.y), "=f"(v.z), "=f"(v.w)
                 : "l"(p), "l"(pol));
    return v;
}

__device__ __forceinline__ float ldg_keep(const float* p, uint64_t pol) {
    float v;
    asm volatile("ld.global.nc.L2::cache_hint.f32 %0, [%1], %2;"
                 : "=f"(v) : "l"(p), "l"(pol));
    return v;
}

__device__ __forceinline__ float sel4(float4 v, int o) {
    float r = (o == 1) ? v.y : v.x;
    r = (o == 2) ? v.z : r;
    r = (o == 3) ? v.w : r;
    return r;
}

__global__ __launch_bounds__(256) void volume_sample_kernel(
    const float* __restrict__ x,
    const float* __restrict__ vol,
    float* __restrict__ out)
{
    int i = blockIdx.x * blockDim.x + threadIdx.x;
    if (i >= N_TOTAL) return;

    uint64_t pol = evict_last_policy();

    // EXTENT=0.5: coord = x/0.5; ix = ((coord+1)*256 - 1)/2 = 256*gx + 127.5
    // .cs coords: evict-first in L1/L2 so the 6MB coord stream never churns
    // volume lines out of L1 (R12 showed plain __ldg here costs +42%).
    float gx = __ldcs(x + 3 * i + 0);
    float gy = __ldcs(x + 3 * i + 1);
    float gz = __ldcs(x + 3 * i + 2);

    float ix = fmaf(gx, 256.0f, 127.5f);
    float iy = fmaf(gy, 256.0f, 127.5f);
    float iz = fmaf(gz, 256.0f, 127.5f);

    float fx0 = floorf(ix);
    float fy0 = floorf(iy);
    float fz0 = floorf(iz);

    float tx = ix - fx0;
    float ty = iy - fy0;
    float tz = iz - fz0;

    int x0 = (int)fx0;
    int y0 = (int)fy0;
    int z0 = (int)fz0;
    int x1 = x0 + 1;
    int y1 = y0 + 1;
    int z1 = z0 + 1;

    bool vx0 = (x0 >= 0) & (x0 < RES);
    bool vx1 = (x1 >= 0) & (x1 < RES);
    bool vy0 = (y0 >= 0) & (y0 < RES);
    bool vy1 = (y1 >= 0) & (y1 < RES);
    bool vz0 = (z0 >= 0) & (z0 < RES);
    bool vz1 = (z1 >= 0) & (z1 < RES);

    int cx0 = min(max(x0, 0), RES - 1);
    int cx1 = min(max(x1, 0), RES - 1);
    int cy0 = min(max(y0, 0), RES - 1);
    int cy1 = min(max(y1, 0), RES - 1);
    int cz0 = min(max(z0, 0), RES - 1);
    int cz1 = min(max(z1, 0), RES - 1);

    long pz0 = (long)cz0 * (RES * RES);
    long pz1 = (long)cz1 * (RES * RES);
    long r00 = pz0 + cy0 * RES;   // (z0, y0)
    long r01 = pz0 + cy1 * RES;   // (z0, y1)
    long r10 = pz1 + cy0 * RES;   // (z1, y0)
    long r11 = pz1 + cy1 * RES;   // (z1, y1)

    int base = cx0 & ~3;          // 16B-aligned; base+3 <= 255 always
    int ao = cx0 - base;          // 0..3
    int d1 = cx1 - base;          // 0..4
    int bo = min(d1, 3);
    bool need_extra = (d1 == 4);  // x1 outside the float4 (~25% of lanes)

    // 4 vector gathers, one per (z,y) row — evict-last priority in L2
    float4 q00 = ldg_keep4(vol + r00 + base, pol);
    float4 q01 = ldg_keep4(vol + r01 + base, pol);
    float4 q10 = ldg_keep4(vol + r10 + base, pol);
    float4 q11 = ldg_keep4(vol + r11 + base, pol);

    float e00 = 0.f, e01 = 0.f, e10 = 0.f, e11 = 0.f;
    if (need_extra) {
        e00 = ldg_keep(vol + r00 + cx1, pol);
        e01 = ldg_keep(vol + r01 + cx1, pol);
        e10 = ldg_keep(vol + r10 + cx1, pol);
        e11 = ldg_keep(vol + r11 + cx1, pol);
    }

    float a00 = sel4(q00, ao), a01 = sel4(q01, ao);
    float a10 = sel4(q10, ao), a11 = sel4(q11, ao);
    float b00 = need_extra ? e00 : sel4(q00, bo);
    float b01 = need_extra ? e01 : sel4(q01, bo);
    float b10 = need_extra ? e10 : sel4(q10, bo);
    float b11 = need_extra ? e11 : sel4(q11, bo);

    a00 = (vz0 & vy0 & vx0) ? a00 : 0.0f;
    b00 = (vz0 & vy0 & vx1) ? b00 : 0.0f;
    a01 = (vz0 & vy1 & vx0) ? a01 : 0.0f;
    b01 = (vz0 & vy1 & vx1) ? b01 : 0.0f;
    a10 = (vz1 & vy0 & vx0) ? a10 : 0.0f;
    b10 = (vz1 & vy0 & vx1) ? b10 : 0.0f;
    a11 = (vz1 & vy1 & vx0) ? a11 : 0.0f;
    b11 = (vz1 & vy1 & vx1) ? b11 : 0.0f;

    float c00 = fmaf(tx, b00 - a00, a00);
    float c01 = fmaf(tx, b01 - a01, a01);
    float c10 = fmaf(tx, b10 - a10, a10);
    float c11 = fmaf(tx, b11 - a11, a11);

    float c0 = fmaf(ty, c01 - c00, c00);
    float c1 = fmaf(ty, c11 - c10, c10);

    float c = fmaf(tz, c1 - c0, c0);

    float r = 100.0f * c;
    asm volatile("st.global.cs.f32 [%0], %1;" :: "l"(out + i), "f"(r) : "memory");
}

extern "C" void kernel_launch(void* const* d_in, const int* in_sizes, int n_in,
                              void* d_out, int out_size)
{
    const float* x   = (const float*)d_in[0];  // [8, 65536, 3] f32
    const float* vol = (const float*)d_in[1];  // [256,256,256] f32
    float* out = (float*)d_out;                // [8, 65536] f32

    int threads = 256;
    int blocks = (N_TOTAL + threads - 1) / threads;
    volume_sample_kernel<<<blocks, threads>>>(x, vol, out);
}

// round 14
// speedup vs baseline: 1.3981x; 1.0019x over previous
#include <cuda_runtime.h>
#include <cstdint>

#define RES 256
#define N_TOTAL (8 * 65536)

__device__ __forceinline__ uint64_t evict_last_policy() {
    uint64_t pol;
    asm("createpolicy.fractional.L2::evict_last.b64 %0, 1.0;" : "=l"(pol));
    return pol;
}

__device__ __forceinline__ float4 ldg_keep4(const float* p, uint64_t pol) {
    float4 v;
    asm volatile("ld.global.nc.L2::cache_hint.v4.f32 {%0,%1,%2,%3}, [%4], %5;"
                 : "=f"(v.x), "=f"(v.y), "=f"(v.z), "=f"(v.w)
                 : "l"(p), "l"(pol));
    return v;
}

__device__ __forceinline__ float ldg_keep(const float* p, uint64_t pol) {
    float v;
    asm volatile("ld.global.nc.L2::cache_hint.f32 %0, [%1], %2;"
                 : "=f"(v) : "l"(p), "l"(pol));
    return v;
}

__device__ __forceinline__ float sel4(float4 v, int o) {
    float r = (o == 1) ? v.y : v.x;
    r = (o == 2) ? v.z : r;
    r = (o == 3) ? v.w : r;
    return r;
}

__global__ __launch_bounds__(256) void volume_sample_kernel(
    const float* __restrict__ x,
    const float* __restrict__ vol,
    float* __restrict__ out)
{
    int i = blockIdx.x * blockDim.x + threadIdx.x;
    if (i >= N_TOTAL) return;

    uint64_t pol = evict_last_policy();

    // EXTENT=0.5: coord = x/0.5; ix = ((coord+1)*256 - 1)/2 = 256*gx + 127.5
    // .cs coords: evict-first so the 6MB coordinate stream never churns
    // volume lines (R12: plain __ldg here cost +42%).
    float gx = __ldcs(x + 3 * i + 0);
    float gy = __ldcs(x + 3 * i + 1);
    float gz = __ldcs(x + 3 * i + 2);

    float ix = fmaf(gx, 256.0f, 127.5f);
    float iy = fmaf(gy, 256.0f, 127.5f);
    float iz = fmaf(gz, 256.0f, 127.5f);

    float fx0 = floorf(ix);
    float fy0 = floorf(iy);
    float fz0 = floorf(iz);

    float tx = ix - fx0;
    float ty = iy - fy0;
    float tz = iz - fz0;

    int x0 = (int)fx0;
    int y0 = (int)fy0;
    int z0 = (int)fz0;
    int x1 = x0 + 1;
    int y1 = y0 + 1;
    int z1 = z0 + 1;

    bool vx0 = (x0 >= 0) & (x0 < RES);
    bool vx1 = (x1 >= 0) & (x1 < RES);
    bool vy0 = (y0 >= 0) & (y0 < RES);
    bool vy1 = (y1 >= 0) & (y1 < RES);
    bool vz0 = (z0 >= 0) & (z0 < RES);
    bool vz1 = (z1 >= 0) & (z1 < RES);

    int cx0 = min(max(x0, 0), RES - 1);
    int cx1 = min(max(x1, 0), RES - 1);
    int cy0 = min(max(y0, 0), RES - 1);
    int cy1 = min(max(y1, 0), RES - 1);
    int cz0 = min(max(z0, 0), RES - 1);
    int cz1 = min(max(z1, 0), RES - 1);

    long pz0 = (long)cz0 * (RES * RES);
    long pz1 = (long)cz1 * (RES * RES);
    long r00 = pz0 + cy0 * RES;   // (z0, y0)
    long r01 = pz0 + cy1 * RES;   // (z0, y1)
    long r10 = pz1 + cy0 * RES;   // (z1, y0)
    long r11 = pz1 + cy1 * RES;   // (z1, y1)

    int base = cx0 & ~3;          // 16B-aligned; base+3 <= 255 always
    int ao = cx0 - base;          // 0..3
    int d1 = cx1 - base;          // 0..4
    int bo = min(d1, 3);
    bool need_extra = (d1 == 4);  // x1 outside the float4 (~25% of lanes)

    // 4 vector gathers, one per (z,y) row — evict-last priority in L2
    float4 q00 = ldg_keep4(vol + r00 + base, pol);
    float4 q01 = ldg_keep4(vol + r01 + base, pol);
    float4 q10 = ldg_keep4(vol + r10 + base, pol);
    float4 q11 = ldg_keep4(vol + r11 + base, pol);

    float e00 = 0.f, e01 = 0.f, e10 = 0.f, e11 = 0.f;
    if (need_extra) {
        e00 = ldg_keep(vol + r00 + cx1, pol);
        e01 = ldg_keep(vol + r01 + cx1, pol);
        e10 = ldg_keep(vol + r10 + cx1, pol);
        e11 = ldg_keep(vol + r11 + cx1, pol);
    }

    float a00 = sel4(q00, ao), a01 = sel4(q01, ao);
    float a10 = sel4(q10, ao), a11 = sel4(q11, ao);
    float b00 = need_extra ? e00 : sel4(q00, bo);
    float b01 = need_extra ? e01 : sel4(q01, bo);
    float b10 = need_extra ? e10 : sel4(q10, bo);
    float b11 = need_extra ? e11 : sel4(q11, bo);

    a00 = (vz0 & vy0 & vx0) ? a00 : 0.0f;
    b00 = (vz0 & vy0 & vx1) ? b00 : 0.0f;
    a01 = (vz0 & vy1 & vx0) ? a01 : 0.0f;
    b01 = (vz0 & vy1 & vx1) ? b01 : 0.0f;
    a10 = (vz1 & vy0 & vx0) ? a10 : 0.0f;
    b10 = (vz1 & vy0 & vx1) ? b10 : 0.0f;
    a11 = (vz1 & vy1 & vx0) ? a11 : 0.0f;
    b11 = (vz1 & vy1 & vx1) ? b11 : 0.0f;

    float c00 = fmaf(tx, b00 - a00, a00);
    float c01 = fmaf(tx, b01 - a01, a01);
    float c10 = fmaf(tx, b10 - a10, a10);
    float c11 = fmaf(tx, b11 - a11, a11);

    float c0 = fmaf(ty, c01 - c00, c00);
    float c1 = fmaf(ty, c11 - c10, c10);

    float c = fmaf(tz, c1 - c0, c0);

    float r = 100.0f * c;
    asm volatile("st.global.cs.f32 [%0], %1;" :: "l"(out + i), "f"(r) : "memory");
}

extern "C" void kernel_launch(void* const* d_in, const int* in_sizes, int n_in,
                              void* d_out, int out_size)
{
    const float* x   = (const float*)d_in[0];  // [8, 65536, 3] f32
    const float* vol = (const float*)d_in[1];  // [256,256,256] f32
    float* out = (float*)d_out;                // [8, 65536] f32

    int threads = 256;
    int blocks = (N_TOTAL + threads - 1) / threads;
    volume_sample_kernel<<<blocks, threads>>>(x, vol, out);
}

// round 15
// speedup vs baseline: 1.4035x; 1.0039x over previous
#include <cuda_runtime.h>
#include <cstdint>

#define RES 256
#define N_TOTAL (8 * 65536)
#define THREADS 128
#define NBLK (N_TOTAL / THREADS / 2)       // 2048 blocks, 2 pts/thread

__device__ __forceinline__ uint64_t evict_last_policy() {
    uint64_t pol;
    asm("createpolicy.fractional.L2::evict_last.b64 %0, 1.0;" : "=l"(pol));
    return pol;
}

__device__ __forceinline__ float4 ldg_keep4(const float* p, uint64_t pol) {
    float4 v;
    asm volatile("ld.global.nc.L2::cache_hint.v4.f32 {%0,%1,%2,%3}, [%4], %5;"
                 : "=f"(v.x), "=f"(v.y), "=f"(v.z), "=f"(v.w)
                 : "l"(p), "l"(pol));
    return v;
}

__device__ __forceinline__ float ldg_keep(const float* p, uint64_t pol) {
    float v;
    asm volatile("ld.global.nc.L2::cache_hint.f32 %0, [%1], %2;"
                 : "=f"(v) : "l"(p), "l"(pol));
    return v;
}

__device__ __forceinline__ float sel4(float4 v, int o) {
    float r = (o == 1) ? v.y : v.x;
    r = (o == 2) ? v.z : r;
    r = (o == 3) ? v.w : r;
    return r;
}

__global__ __launch_bounds__(THREADS) void volume_sample_kernel(
    const float* __restrict__ x,
    const float* __restrict__ vol,
    float* __restrict__ out)
{
    int t = blockIdx.x * THREADS + threadIdx.x;     // 0..262143 (pair index)

    uint64_t pol = evict_last_policy();

    // coords for points 2t, 2t+1: 6 floats via 3x .cs float2 loads
    // (.cs = evict-first: R12 proved plain-cached coords poison L1 → +42%)
    const float2* cp = (const float2*)x + (size_t)t * 3;
    float2 c0 = __ldcs(cp + 0);
    float2 c1 = __ldcs(cp + 1);
    float2 c2 = __ldcs(cp + 2);

    float gxa[2] = { c0.x, c1.y };
    float gya[2] = { c0.y, c2.x };
    float gza[2] = { c1.x, c2.y };

    float tx[2], ty[2], tz[2];
    long  row[2][4];
    int   basei[2], ao[2], bo[2], cx1a[2];
    bool  ex[2];
    bool  m_a[2][4], m_b[2][4];

    #pragma unroll
    for (int k = 0; k < 2; k++) {
        // EXTENT=0.5 fold: ix = 256*gx + 127.5
        float ix = fmaf(gxa[k], 256.0f, 127.5f);
        float iy = fmaf(gya[k], 256.0f, 127.5f);
        float iz = fmaf(gza[k], 256.0f, 127.5f);

        float fx0 = floorf(ix), fy0 = floorf(iy), fz0 = floorf(iz);
        tx[k] = ix - fx0;  ty[k] = iy - fy0;  tz[k] = iz - fz0;

        int x0 = (int)fx0, y0 = (int)fy0, z0 = (int)fz0;
        int x1 = x0 + 1,   y1 = y0 + 1,   z1 = z0 + 1;

        bool vx0 = (x0 >= 0) & (x0 < RES);
        bool vx1 = (x1 >= 0) & (x1 < RES);
        bool vy0 = (y0 >= 0) & (y0 < RES);
        bool vy1 = (y1 >= 0) & (y1 < RES);
        bool vz0 = (z0 >= 0) & (z0 < RES);
        bool vz1 = (z1 >= 0) & (z1 < RES);

        int cx0 = min(max(x0, 0), RES - 1);
        int cx1 = min(max(x1, 0), RES - 1);
        int cy0 = min(max(y0, 0), RES - 1);
        int cy1 = min(max(y1, 0), RES - 1);
        int cz0 = min(max(z0, 0), RES - 1);
        int cz1 = min(max(z1, 0), RES - 1);

        long pz0 = (long)cz0 * (RES * RES);
        long pz1 = (long)cz1 * (RES * RES);
        row[k][0] = pz0 + cy0 * RES;   // (z0,y0)
        row[k][1] = pz0 + cy1 * RES;   // (z0,y1)
        row[k][2] = pz1 + cy0 * RES;   // (z1,y0)
        row[k][3] = pz1 + cy1 * RES;   // (z1,y1)

        basei[k] = cx0 & ~3;           // 16B aligned, always in-bounds
        ao[k]    = cx0 - basei[k];
        int d1   = cx1 - basei[k];
        bo[k]    = min(d1, 3);
        ex[k]    = (d1 == 4);
        cx1a[k]  = cx1;

        m_a[k][0] = vz0 & vy0 & vx0;  m_b[k][0] = vz0 & vy0 & vx1;
        m_a[k][1] = vz0 & vy1 & vx0;  m_b[k][1] = vz0 & vy1 & vx1;
        m_a[k][2] = vz1 & vy0 & vx0;  m_b[k][2] = vz1 & vy0 & vx1;
        m_a[k][3] = vz1 & vy1 & vx0;  m_b[k][3] = vz1 & vy1 & vx1;
    }

    // ---- 8 independent v4 gathers front-batched (deep MLP per warp-slot) ----
    float4 q[2][4];
    #pragma unroll
    for (int k = 0; k < 2; k++)
        #pragma unroll
        for (int r = 0; r < 4; r++)
            q[k][r] = ldg_keep4(vol + row[k][r] + basei[k], pol);

    float e[2][4] = {{0.f,0.f,0.f,0.f},{0.f,0.f,0.f,0.f}};
    #pragma unroll
    for (int k = 0; k < 2; k++)
        if (ex[k])
            #pragma unroll
            for (int r = 0; r < 4; r++)
                e[k][r] = ldg_keep(vol + row[k][r] + cx1a[k], pol);

    // ---- blend + trilinear ----
    float res[2];
    #pragma unroll
    for (int k = 0; k < 2; k++) {
        float a[4], b[4];
        #pragma unroll
        for (int r = 0; r < 4; r++) {
            float av = sel4(q[k][r], ao[k]);
            float bv = ex[k] ? e[k][r] : sel4(q[k][r], bo[k]);
            a[r] = m_a[k][r] ? av : 0.0f;
            b[r] = m_b[k][r] ? bv : 0.0f;
        }
        float c00 = fmaf(tx[k], b[0] - a[0], a[0]);
        float c01 = fmaf(tx[k], b[1] - a[1], a[1]);
        float c10 = fmaf(tx[k], b[2] - a[2], a[2]);
        float c11 = fmaf(tx[k], b[3] - a[3], a[3]);
        float c0  = fmaf(ty[k], c01 - c00, c00);
        float c1  = fmaf(ty[k], c11 - c10, c10);
        res[k] = 100.0f * fmaf(tz[k], c1 - c0, c0);
    }

    asm volatile("st.global.cs.v2.f32 [%0], {%1, %2};"
                 :: "l"(out + 2 * (size_t)t), "f"(res[0]), "f"(res[1]) : "memory");
}

extern "C" void kernel_launch(void* const* d_in, const int* in_sizes, int n_in,
                              void* d_out, int out_size)
{
    const float* x   = (const float*)d_in[0];  // [8, 65536, 3] f32
    const float* vol = (const float*)d_in[1];  // [256,256,256] f32
    float* out = (float*)d_out;                // [8, 65536] f32

    volume_sample_kernel<<<NBLK, THREADS>>>(x, vol, out);
}